// round 1
// baseline (speedup 1.0000x reference)
#include <cuda_runtime.h>

#define NQ1   16384      // total queries (B * 1024)
#define NS2   65536      // total sources (B * 4096)
#define N1P_  1024
#define N2P_  4096
#define DIN_  64
#define KNB   32
#define H1_   128
#define H2_   256

// ---- scratch (device globals; allocation-free) ----
__device__ int   g_nbr[NQ1 * KNB];
__device__ int   g_cnt[NQ1];
__device__ float g_A2[(size_t)NS2 * H1_];   // 32 MB, L2-resident
__device__ float g_P1[(size_t)NQ1 * H1_];   // 8 MB

// =====================================================================
// Kernel A: ball query — warp per query, ordered scan with ballot/popc.
// Keeps first K=32 in-ball sources by index (exact tie-break), early exit.
// =====================================================================
__global__ void __launch_bounds__(256)
ball_query_kernel(const float* __restrict__ pos1, const float* __restrict__ pos2) {
    int q    = blockIdx.x * 8 + (threadIdx.x >> 5);
    int lane = threadIdx.x & 31;
    int base = (q >> 10) << 12;                    // batch * 4096

    float qx = pos1[3*q+0], qy = pos1[3*q+1], qz = pos1[3*q+2];
    float q2 = qx*qx + qy*qy + qz*qz;

    int cnt = 0;
    for (int j0 = 0; j0 < N2P_ && cnt < KNB; j0 += 32) {
        int j = j0 + lane;
        const float* p = pos2 + (size_t)(base + j) * 3;
        float px = p[0], py = p[1], pz = p[2];
        // mirror reference formula: |p1|^2 + |p2|^2 - 2 p1.p2
        float sq = q2 + (px*px + py*py + pz*pz) - 2.0f*(qx*px + qy*py + qz*pz);
        bool hit = sq <= 0.04f;
        unsigned m = __ballot_sync(0xffffffffu, hit);
        if (hit) {
            int pos = cnt + __popc(m & ((1u << lane) - 1u));
            if (pos < KNB) g_nbr[q*KNB + pos] = base + j;
        }
        cnt += __popc(m);
    }
    if (lane == 0) g_cnt[q] = cnt < KNB ? cnt : KNB;
}

// =====================================================================
// Kernel B: A2[s][j] = b1[j] + x2[s]·W1[0:64][j] + pos2[s]·W1[64:67][j]
// 16 sources per block, W1 + x2-tile in smem.
// =====================================================================
__global__ void __launch_bounds__(256)
precompute_A2_kernel(const float* __restrict__ x2, const float* __restrict__ pos2,
                     const float* __restrict__ W1, const float* __restrict__ b1) {
    __shared__ float W1s[67 * 128];
    __shared__ float x2s[16][64];
    __shared__ float p2s[16][3];

    int t  = threadIdx.x;
    int s0 = blockIdx.x * 16;
    for (int i = t; i < 67*128; i += 256) W1s[i] = W1[i];
    for (int i = t; i < 16*64;  i += 256) x2s[i >> 6][i & 63] = x2[(size_t)s0*64 + i];
    if (t < 48) p2s[t/3][t%3] = pos2[(size_t)s0*3 + t];
    __syncthreads();

    int sl = t >> 4;
    int c0 = (t & 15) * 8;

    float acc[8];
    #pragma unroll
    for (int j = 0; j < 8; j++) acc[j] = b1[c0 + j];

    #pragma unroll 4
    for (int c = 0; c < 64; c++) {
        float xv = x2s[sl][c];
        const float* w = &W1s[c*128 + c0];
        #pragma unroll
        for (int j = 0; j < 8; j++) acc[j] = fmaf(xv, w[j], acc[j]);
    }
    #pragma unroll
    for (int d = 0; d < 3; d++) {
        float pv = p2s[sl][d];
        const float* w = &W1s[(64 + d)*128 + c0];
        #pragma unroll
        for (int j = 0; j < 8; j++) acc[j] = fmaf(pv, w[j], acc[j]);
    }

    float* dst = &g_A2[(size_t)(s0 + sl)*128 + c0];
    #pragma unroll
    for (int j = 0; j < 8; j++) dst[j] = acc[j];
}

// =====================================================================
// Kernel C: P1[q][j] = pos1[q]·W1[64:67][j]   (2M elems, trivial)
// =====================================================================
__global__ void __launch_bounds__(256)
precompute_P1_kernel(const float* __restrict__ pos1, const float* __restrict__ W1) {
    int idx = blockIdx.x * 256 + threadIdx.x;        // NQ1*128 total
    int q = idx >> 7, j = idx & 127;
    float a = pos1[3*q+0], b = pos1[3*q+1], c = pos1[3*q+2];
    g_P1[idx] = fmaf(a, W1[64*128 + j], fmaf(b, W1[65*128 + j], c * W1[66*128 + j]));
}

// =====================================================================
// Kernel D: fused  m1 = relu(A2[src] - P1[q]);  out = max_rows relu(m1@W2+b2)
// 4 queries / block (132 rows). W2 (128KB) + m1 (66KB) in smem.
// Thread: (query-group qg = t>>6, 4 output cols c0 = (t&63)*4).
// Row loop is warp-uniform (all 64 threads of a qg share the query),
// so invalid neighbor rows are skipped with no divergence.
// =====================================================================
__global__ void __launch_bounds__(256)
fused_layer2_kernel(const float* __restrict__ W2, const float* __restrict__ b2,
                    float* __restrict__ out) {
    extern __shared__ float smemD[];
    float* W2s = smemD;                 // 128*256 = 32768 floats
    float* m1s = smemD + 32768;         // 4 * 33*128 = 16896 floats
    __shared__ int s_nbr[4 * 33];
    __shared__ int s_cnt[4];

    int t  = threadIdx.x;
    int qg = t >> 6;
    int cg = t & 63;
    int q  = blockIdx.x * 4 + qg;

    // stage W2 into smem (coalesced float4)
    for (int i = t; i < (128*256)/4; i += 256)
        ((float4*)W2s)[i] = ((const float4*)W2)[i];

    if (cg < 32)  s_nbr[qg*33 + cg] = g_nbr[q*KNB + cg];
    if (cg == 32) s_nbr[qg*33 + 32] = q;           // self-loop source index
    if (cg == 33) s_cnt[qg] = g_cnt[q];
    __syncthreads();

    int cnt = s_cnt[qg];
    float* m1q = m1s + qg * (33*128);
    const float* P1q = g_P1 + (size_t)q * 128;

    // phase A: build m1 rows (valid neighbors + self). float4 per element.
    for (int e = cg; e < 33*32; e += 64) {
        int r = e >> 5, k4 = e & 31;
        if (r < cnt || r == 32) {
            int src = s_nbr[qg*33 + r];
            float4 a = *(const float4*)(g_A2 + (size_t)src*128 + k4*4);
            float4 p = *(const float4*)(P1q + k4*4);
            float4 v;
            v.x = fmaxf(a.x - p.x, 0.0f);
            v.y = fmaxf(a.y - p.y, 0.0f);
            v.z = fmaxf(a.z - p.z, 0.0f);
            v.w = fmaxf(a.w - p.w, 0.0f);
            *(float4*)(m1q + r*128 + k4*4) = v;
        }
    }
    __syncthreads();

    // phase B: per thread, 4 cols; dot over k=128 per row, relu+max fold.
    int c0 = cg * 4;
    float4 bv = *(const float4*)(b2 + c0);
    float mx0 = 0.f, mx1 = 0.f, mx2 = 0.f, mx3 = 0.f;   // relu floor; self always valid

    for (int ri = 0; ri <= cnt; ri++) {          // ri==0 -> self row (32)
        int r = (ri == 0) ? 32 : (ri - 1);
        const float* mrow = m1q + r * 128;
        float a0 = 0.f, a1 = 0.f, a2 = 0.f, a3 = 0.f;
        #pragma unroll 4
        for (int k = 0; k < 128; k += 4) {
            float4 mv = *(const float4*)(mrow + k);
            float4 w;
            w = *(const float4*)(W2s + (k+0)*256 + c0);
            a0 = fmaf(mv.x, w.x, a0); a1 = fmaf(mv.x, w.y, a1);
            a2 = fmaf(mv.x, w.z, a2); a3 = fmaf(mv.x, w.w, a3);
            w = *(const float4*)(W2s + (k+1)*256 + c0);
            a0 = fmaf(mv.y, w.x, a0); a1 = fmaf(mv.y, w.y, a1);
            a2 = fmaf(mv.y, w.z, a2); a3 = fmaf(mv.y, w.w, a3);
            w = *(const float4*)(W2s + (k+2)*256 + c0);
            a0 = fmaf(mv.z, w.x, a0); a1 = fmaf(mv.z, w.y, a1);
            a2 = fmaf(mv.z, w.z, a2); a3 = fmaf(mv.z, w.w, a3);
            w = *(const float4*)(W2s + (k+3)*256 + c0);
            a0 = fmaf(mv.w, w.x, a0); a1 = fmaf(mv.w, w.y, a1);
            a2 = fmaf(mv.w, w.z, a2); a3 = fmaf(mv.w, w.w, a3);
        }
        mx0 = fmaxf(mx0, fmaxf(a0 + bv.x, 0.0f));
        mx1 = fmaxf(mx1, fmaxf(a1 + bv.y, 0.0f));
        mx2 = fmaxf(mx2, fmaxf(a2 + bv.z, 0.0f));
        mx3 = fmaxf(mx3, fmaxf(a3 + bv.w, 0.0f));
    }

    float4 o; o.x = mx0; o.y = mx1; o.z = mx2; o.w = mx3;
    *(float4*)(out + (size_t)q*256 + c0) = o;
}

// =====================================================================
// launch
// inputs: 0:x1 1:pos1 2:batch1 3:x2 4:pos2 5:batch2 6:W1 7:b1 8:W2 9:b2
// =====================================================================
extern "C" void kernel_launch(void* const* d_in, const int* in_sizes, int n_in,
                              void* d_out, int out_size) {
    const float* pos1 = (const float*)d_in[1];
    const float* x2   = (const float*)d_in[3];
    const float* pos2 = (const float*)d_in[4];
    const float* W1   = (const float*)d_in[6];
    const float* b1   = (const float*)d_in[7];
    const float* W2   = (const float*)d_in[8];
    const float* b2   = (const float*)d_in[9];
    float* out = (float*)d_out;

    ball_query_kernel<<<NQ1/8, 256>>>(pos1, pos2);
    precompute_A2_kernel<<<NS2/16, 256>>>(x2, pos2, W1, b1);
    precompute_P1_kernel<<<(NQ1*128)/256, 256>>>(pos1, W1);

    size_t smem_bytes = (size_t)(32768 + 16896) * sizeof(float);   // 198656 B
    cudaFuncSetAttribute(fused_layer2_kernel,
                         cudaFuncAttributeMaxDynamicSharedMemorySize,
                         (int)smem_bytes);
    fused_layer2_kernel<<<NQ1/4, 256, smem_bytes>>>(W2, b2, out);
}

// round 4
// speedup vs baseline: 2.2184x; 2.2184x over previous
#include <cuda_runtime.h>

#define NQ1   16384      // total queries (B * 1024)
#define NS2   65536      // total sources (B * 4096)
#define N2P_  4096
#define KNB   32
#define H1_   128
#define H2_   256
#define RT    11         // row tile: 33 rows = 3 tiles of 11

// ---- scratch (device globals; allocation-free) ----
__device__ int   g_nbr[NQ1 * KNB];
__device__ int   g_cnt[NQ1];
__device__ float g_A2[(size_t)NS2 * H1_];   // 32 MB, L2-resident
__device__ float g_P1[(size_t)NQ1 * H1_];   // 8 MB

// =====================================================================
// Kernel A: ball query — warp per query, ordered scan with ballot/popc.
// =====================================================================
__global__ void __launch_bounds__(256)
ball_query_kernel(const float* __restrict__ pos1, const float* __restrict__ pos2) {
    int q    = blockIdx.x * 8 + (threadIdx.x >> 5);
    int lane = threadIdx.x & 31;
    int base = (q >> 10) << 12;                    // batch * 4096

    float qx = pos1[3*q+0], qy = pos1[3*q+1], qz = pos1[3*q+2];
    float q2 = qx*qx + qy*qy + qz*qz;

    int cnt = 0;
    for (int j0 = 0; j0 < N2P_ && cnt < KNB; j0 += 32) {
        int j = j0 + lane;
        const float* p = pos2 + (size_t)(base + j) * 3;
        float px = p[0], py = p[1], pz = p[2];
        float sq = q2 + (px*px + py*py + pz*pz) - 2.0f*(qx*px + qy*py + qz*pz);
        bool hit = sq <= 0.04f;
        unsigned m = __ballot_sync(0xffffffffu, hit);
        if (hit) {
            int pos = cnt + __popc(m & ((1u << lane) - 1u));
            if (pos < KNB) g_nbr[q*KNB + pos] = base + j;
        }
        cnt += __popc(m);
    }
    if (lane == 0) g_cnt[q] = cnt < KNB ? cnt : KNB;
}

// =====================================================================
// Kernel B: A2[s][j] = b1[j] + x2[s]·W1[0:64][j] + pos2[s]·W1[64:67][j]
// =====================================================================
__global__ void __launch_bounds__(256)
precompute_A2_kernel(const float* __restrict__ x2, const float* __restrict__ pos2,
                     const float* __restrict__ W1, const float* __restrict__ b1) {
    __shared__ float W1s[67 * 128];
    __shared__ float x2s[16][64];
    __shared__ float p2s[16][3];

    int t  = threadIdx.x;
    int s0 = blockIdx.x * 16;
    for (int i = t; i < 67*128; i += 256) W1s[i] = W1[i];
    for (int i = t; i < 16*64;  i += 256) x2s[i >> 6][i & 63] = x2[(size_t)s0*64 + i];
    if (t < 48) p2s[t/3][t%3] = pos2[(size_t)s0*3 + t];
    __syncthreads();

    int sl = t >> 4;
    int c0 = (t & 15) * 8;

    float acc[8];
    #pragma unroll
    for (int j = 0; j < 8; j++) acc[j] = b1[c0 + j];

    #pragma unroll 4
    for (int c = 0; c < 64; c++) {
        float xv = x2s[sl][c];
        const float* w = &W1s[c*128 + c0];
        #pragma unroll
        for (int j = 0; j < 8; j++) acc[j] = fmaf(xv, w[j], acc[j]);
    }
    #pragma unroll
    for (int d = 0; d < 3; d++) {
        float pv = p2s[sl][d];
        const float* w = &W1s[(64 + d)*128 + c0];
        #pragma unroll
        for (int j = 0; j < 8; j++) acc[j] = fmaf(pv, w[j], acc[j]);
    }

    float* dst = &g_A2[(size_t)(s0 + sl)*128 + c0];
    #pragma unroll
    for (int j = 0; j < 8; j++) dst[j] = acc[j];
}

// =====================================================================
// Kernel C: P1[q][j] = pos1[q]·W1[64:67][j]
// =====================================================================
__global__ void __launch_bounds__(256)
precompute_P1_kernel(const float* __restrict__ pos1, const float* __restrict__ W1) {
    int idx = blockIdx.x * 256 + threadIdx.x;
    int q = idx >> 7, j = idx & 127;
    float a = pos1[3*q+0], b = pos1[3*q+1], c = pos1[3*q+2];
    g_P1[idx] = fmaf(a, W1[64*128 + j], fmaf(b, W1[65*128 + j], c * W1[66*128 + j]));
}

// =====================================================================
// Kernel D: fused  m1 = relu(A2[src] - P1[q]);  out = max_rows relu(m1@W2+b2)
// 4 queries/block. Row-blocked: each thread holds 11 rows x 4 cols of
// accumulators, so every W2 float4 load is reused 11x, and m1 loads are
// warp-broadcast (1 crossbar phase). Invalid rows padded with the always-
// valid self row (max idempotent) -> uniform control flow.
// =====================================================================
__global__ void __launch_bounds__(256)
fused_layer2_kernel(const float* __restrict__ W2, const float* __restrict__ b2,
                    float* __restrict__ out) {
    extern __shared__ float smemD[];
    float* W2s = smemD;                 // 128*256 = 32768 floats (128 KB)
    float* m1s = smemD + 32768;         // 4 * 33*128 = 16896 floats (66 KB)
    __shared__ int s_nbr[4 * 33];
    __shared__ int s_cnt[4];

    int t  = threadIdx.x;
    int qg = t >> 6;
    int cg = t & 63;
    int q  = blockIdx.x * 4 + qg;

    // stage W2 into smem (coalesced float4)
    for (int i = t; i < (128*256)/4; i += 256)
        ((float4*)W2s)[i] = ((const float4*)W2)[i];

    if (cg < 32)  s_nbr[qg*33 + cg] = g_nbr[q*KNB + cg];
    if (cg == 32) s_nbr[qg*33 + 32] = q;           // self-loop source index
    if (cg == 33) s_cnt[qg] = g_cnt[q];
    __syncthreads();

    int cnt = s_cnt[qg];
    float* m1q = m1s + qg * (33*128);
    const float* P1q = g_P1 + (size_t)q * 128;

    // phase A: build m1 rows (valid neighbors + self)
    for (int e = cg; e < 33*32; e += 64) {
        int r = e >> 5, k4 = e & 31;
        if (r < cnt || r == 32) {
            int src = s_nbr[qg*33 + r];
            float4 a = *(const float4*)(g_A2 + (size_t)src*128 + k4*4);
            float4 p = *(const float4*)(P1q + k4*4);
            float4 v;
            v.x = fmaxf(a.x - p.x, 0.0f);
            v.y = fmaxf(a.y - p.y, 0.0f);
            v.z = fmaxf(a.z - p.z, 0.0f);
            v.w = fmaxf(a.w - p.w, 0.0f);
            *(float4*)(m1q + r*128 + k4*4) = v;
        }
    }
    __syncthreads();

    // phase B: row-blocked GEMM + relu + max fold
    int c0 = cg * 4;
    float4 bv = *(const float4*)(b2 + c0);
    float mx0 = 0.f, mx1 = 0.f, mx2 = 0.f, mx3 = 0.f;

    int total  = cnt + 1;                  // valid neighbor rows + self
    int ntiles = (total + RT - 1) / RT;    // <= 3

    for (int tile = 0; tile < ntiles; tile++) {
        int jbase = tile * RT;
        // row offsets into m1q (pad with self row 32; exact under max)
        int roff[RT];
        #pragma unroll
        for (int i = 0; i < RT; i++) {
            int j = jbase + i;
            roff[i] = ((j < cnt) ? j : 32) * 128;
        }

        float acc[RT][4];
        #pragma unroll
        for (int i = 0; i < RT; i++) {
            acc[i][0] = 0.f; acc[i][1] = 0.f; acc[i][2] = 0.f; acc[i][3] = 0.f;
        }

        #pragma unroll 1
        for (int k = 0; k < 128; k += 4) {
            float4 w0 = *(const float4*)(W2s + (k+0)*256 + c0);
            float4 w1 = *(const float4*)(W2s + (k+1)*256 + c0);
            float4 w2 = *(const float4*)(W2s + (k+2)*256 + c0);
            float4 w3 = *(const float4*)(W2s + (k+3)*256 + c0);
            #pragma unroll
            for (int i = 0; i < RT; i++) {
                float4 mv = *(const float4*)(m1q + roff[i] + k);   // broadcast
                acc[i][0] = fmaf(mv.x, w0.x, acc[i][0]);
                acc[i][1] = fmaf(mv.x, w0.y, acc[i][1]);
                acc[i][2] = fmaf(mv.x, w0.z, acc[i][2]);
                acc[i][3] = fmaf(mv.x, w0.w, acc[i][3]);
                acc[i][0] = fmaf(mv.y, w1.x, acc[i][0]);
                acc[i][1] = fmaf(mv.y, w1.y, acc[i][1]);
                acc[i][2] = fmaf(mv.y, w1.z, acc[i][2]);
                acc[i][3] = fmaf(mv.y, w1.w, acc[i][3]);
                acc[i][0] = fmaf(mv.z, w2.x, acc[i][0]);
                acc[i][1] = fmaf(mv.z, w2.y, acc[i][1]);
                acc[i][2] = fmaf(mv.z, w2.z, acc[i][2]);
                acc[i][3] = fmaf(mv.z, w2.w, acc[i][3]);
                acc[i][0] = fmaf(mv.w, w3.x, acc[i][0]);
                acc[i][1] = fmaf(mv.w, w3.y, acc[i][1]);
                acc[i][2] = fmaf(mv.w, w3.z, acc[i][2]);
                acc[i][3] = fmaf(mv.w, w3.w, acc[i][3]);
            }
        }

        #pragma unroll
        for (int i = 0; i < RT; i++) {
            mx0 = fmaxf(mx0, fmaxf(acc[i][0] + bv.x, 0.0f));
            mx1 = fmaxf(mx1, fmaxf(acc[i][1] + bv.y, 0.0f));
            mx2 = fmaxf(mx2, fmaxf(acc[i][2] + bv.z, 0.0f));
            mx3 = fmaxf(mx3, fmaxf(acc[i][3] + bv.w, 0.0f));
        }
    }

    float4 o; o.x = mx0; o.y = mx1; o.z = mx2; o.w = mx3;
    *(float4*)(out + (size_t)q*256 + c0) = o;
}

// =====================================================================
// launch
// inputs: 0:x1 1:pos1 2:batch1 3:x2 4:pos2 5:batch2 6:W1 7:b1 8:W2 9:b2
// =====================================================================
extern "C" void kernel_launch(void* const* d_in, const int* in_sizes, int n_in,
                              void* d_out, int out_size) {
    const float* pos1 = (const float*)d_in[1];
    const float* x2   = (const float*)d_in[3];
    const float* pos2 = (const float*)d_in[4];
    const float* W1   = (const float*)d_in[6];
    const float* b1   = (const float*)d_in[7];
    const float* W2   = (const float*)d_in[8];
    const float* b2   = (const float*)d_in[9];
    float* out = (float*)d_out;

    ball_query_kernel<<<NQ1/8, 256>>>(pos1, pos2);
    precompute_A2_kernel<<<NS2/16, 256>>>(x2, pos2, W1, b1);
    precompute_P1_kernel<<<(NQ1*128)/256, 256>>>(pos1, W1);

    size_t smem_bytes = (size_t)(32768 + 16896) * sizeof(float);   // 198656 B
    cudaFuncSetAttribute(fused_layer2_kernel,
                         cudaFuncAttributeMaxDynamicSharedMemorySize,
                         (int)smem_bytes);
    fused_layer2_kernel<<<NQ1/4, 256, smem_bytes>>>(W2, b2, out);
}

// round 8
// speedup vs baseline: 2.8963x; 1.3055x over previous
#include <cuda_runtime.h>
#include <cuda_bf16.h>
#include <cstdint>

#define NQ1   16384      // total queries (B * 1024)
#define NS2   65536      // total sources (B * 4096)
#define N2P_  4096
#define KNB   32

// ---- scratch (device globals; allocation-free) ----
__device__ int   g_nbr[NQ1 * KNB];
__device__ int   g_cnt[NQ1];
__device__ float g_A2[(size_t)NS2 * 128];   // 32 MB, L2-resident
__device__ float g_P1[(size_t)NQ1 * 128];   // 8 MB

// ===================== warp-MMA helpers (plain sm_80+ PTX) =====================
__device__ __forceinline__ uint32_t smem_u32(const void* p) {
    uint32_t a;
    asm("{ .reg .u64 t; cvta.to.shared.u64 t, %1; cvt.u32.u64 %0, t; }"
        : "=r"(a) : "l"(p));
    return a;
}
__device__ __forceinline__ void ldsm_x4(uint32_t& r0, uint32_t& r1,
                                        uint32_t& r2, uint32_t& r3, uint32_t a) {
    asm volatile("ldmatrix.sync.aligned.m8n8.x4.shared.b16 {%0,%1,%2,%3}, [%4];"
                 : "=r"(r0), "=r"(r1), "=r"(r2), "=r"(r3) : "r"(a));
}
__device__ __forceinline__ void ldsm_x2(uint32_t& r0, uint32_t& r1, uint32_t a) {
    asm volatile("ldmatrix.sync.aligned.m8n8.x2.shared.b16 {%0,%1}, [%2];"
                 : "=r"(r0), "=r"(r1) : "r"(a));
}
__device__ __forceinline__ void mma_bf16(float* c, const uint32_t* a,
                                         uint32_t b0, uint32_t b1) {
    asm volatile(
        "mma.sync.aligned.m16n8k16.row.col.f32.bf16.bf16.f32 "
        "{%0,%1,%2,%3}, {%4,%5,%6,%7}, {%8,%9}, {%0,%1,%2,%3};"
        : "+f"(c[0]), "+f"(c[1]), "+f"(c[2]), "+f"(c[3])
        : "r"(a[0]), "r"(a[1]), "r"(a[2]), "r"(a[3]), "r"(b0), "r"(b1));
}

// =====================================================================
// Kernel 0: zero out (relu >= 0, so 0 is the identity for the max fold)
// =====================================================================
__global__ void zero_out_kernel(float4* __restrict__ out) {
    float4 z; z.x = 0.f; z.y = 0.f; z.z = 0.f; z.w = 0.f;
    out[blockIdx.x * 256 + threadIdx.x] = z;
}

// =====================================================================
// Kernel A: ball query — warp per query, ordered scan with ballot/popc.
// =====================================================================
__global__ void __launch_bounds__(256)
ball_query_kernel(const float* __restrict__ pos1, const float* __restrict__ pos2) {
    int q    = blockIdx.x * 8 + (threadIdx.x >> 5);
    int lane = threadIdx.x & 31;
    int base = (q >> 10) << 12;                    // batch * 4096

    float qx = pos1[3*q+0], qy = pos1[3*q+1], qz = pos1[3*q+2];
    float q2 = qx*qx + qy*qy + qz*qz;

    int cnt = 0;
    for (int j0 = 0; j0 < N2P_ && cnt < KNB; j0 += 32) {
        int j = j0 + lane;
        const float* p = pos2 + (size_t)(base + j) * 3;
        float px = p[0], py = p[1], pz = p[2];
        float sq = q2 + (px*px + py*py + pz*pz) - 2.0f*(qx*px + qy*py + qz*pz);
        bool hit = sq <= 0.04f;
        unsigned m = __ballot_sync(0xffffffffu, hit);
        if (hit) {
            int pos = cnt + __popc(m & ((1u << lane) - 1u));
            if (pos < KNB) g_nbr[q*KNB + pos] = base + j;
        }
        cnt += __popc(m);
    }
    if (lane == 0) g_cnt[q] = cnt < KNB ? cnt : KNB;
}

// =====================================================================
// Kernel B: A2[s][j] = b1[j] + x2[s]·W1[0:64][j] + pos2[s]·W1[64:67][j]
// =====================================================================
__global__ void __launch_bounds__(256)
precompute_A2_kernel(const float* __restrict__ x2, const float* __restrict__ pos2,
                     const float* __restrict__ W1, const float* __restrict__ b1) {
    __shared__ float W1s[67 * 128];
    __shared__ float x2s[16][64];
    __shared__ float p2s[16][3];

    int t  = threadIdx.x;
    int s0 = blockIdx.x * 16;
    for (int i = t; i < 67*128; i += 256) W1s[i] = W1[i];
    for (int i = t; i < 16*64;  i += 256) x2s[i >> 6][i & 63] = x2[(size_t)s0*64 + i];
    if (t < 48) p2s[t/3][t%3] = pos2[(size_t)s0*3 + t];
    __syncthreads();

    int sl = t >> 4;
    int c0 = (t & 15) * 8;

    float acc[8];
    #pragma unroll
    for (int j = 0; j < 8; j++) acc[j] = b1[c0 + j];

    #pragma unroll 4
    for (int c = 0; c < 64; c++) {
        float xv = x2s[sl][c];
        const float* w = &W1s[c*128 + c0];
        #pragma unroll
        for (int j = 0; j < 8; j++) acc[j] = fmaf(xv, w[j], acc[j]);
    }
    #pragma unroll
    for (int d = 0; d < 3; d++) {
        float pv = p2s[sl][d];
        const float* w = &W1s[(64 + d)*128 + c0];
        #pragma unroll
        for (int j = 0; j < 8; j++) acc[j] = fmaf(pv, w[j], acc[j]);
    }

    float* dst = &g_A2[(size_t)(s0 + sl)*128 + c0];
    #pragma unroll
    for (int j = 0; j < 8; j++) dst[j] = acc[j];
}

// =====================================================================
// Kernel C: P1[q][j] = pos1[q]·W1[64:67][j]
// =====================================================================
__global__ void __launch_bounds__(256)
precompute_P1_kernel(const float* __restrict__ pos1, const float* __restrict__ W1) {
    int idx = blockIdx.x * 256 + threadIdx.x;
    int q = idx >> 7, j = idx & 127;
    float a = pos1[3*q+0], b = pos1[3*q+1], c = pos1[3*q+2];
    g_P1[idx] = fmaf(a, W1[64*128 + j], fmaf(b, W1[65*128 + j], c * W1[66*128 + j]));
}

// =====================================================================
// Kernel D: bf16 3-term split GEMM on mma.sync + max epilogue.
//
// Tiles of M=128 rows x K=128 x N=256:
//   blocks [0, 4096):  neighbor tiles = 4 queries x 32 neighbor rows
//                      (rows j>=cnt padded with the self row; exact under max)
//   blocks [4096, 4224): self tiles = 128 consecutive queries' self rows
//
// m1 = relu(A2[src]-P1[q]) and W2 split to bf16 hi+lo.
// D = Ah*Bh + Ah*Bl + Al*Bh (fp32 accum in regs; residual ~2^-16).
// smem: A[128][136] bf16 (stride 272B, ldmatrix conflict-free), B[256][136].
// 16 warps: warp = M-strip 32 rows (one query, neighbor case) x N-strip 64.
// Epilogue: relu(D+b2) then intra-warp shfl max over rows; atomicMax on
// float bits (exact for >=0; out zero-initialized).
// =====================================================================
#define STR_B   272u        // row stride in bytes (136 bf16)
#define OFF_AHI 0u
#define OFF_ALO 34816u
#define OFF_BHI 69632u
#define OFF_BLO 139264u
#define DSMEM_BYTES 208896

__global__ void __launch_bounds__(512)
mma_layer2_kernel(const float* __restrict__ W2, const float* __restrict__ b2,
                  float* __restrict__ out) {
    extern __shared__ char smem[];
    __shared__ int   s_src[128];
    __shared__ float b2s[256];

    int t = threadIdx.x, w = t >> 5, lane = t & 31;
    bool is_self = (blockIdx.x >= 4096);
    int tile = is_self ? (int)blockIdx.x - 4096 : (int)blockIdx.x;

    if (t < 256) b2s[t] = b2[t];
    if (t < 128) {
        int src;
        if (is_self) {
            src = tile * 128 + t;
        } else {
            int q = tile * 4 + (t >> 5);
            int j = t & 31;
            src = (j < g_cnt[q]) ? g_nbr[q * KNB + j] : q;
        }
        s_src[t] = src;
    }
    __syncthreads();

    // ---- stage W2 -> B_hi/B_lo as [n][k] rows (stride 272B) ----
    const float4* W2f4 = (const float4*)W2;
    for (int p = t; p < 4096; p += 512) {
        int k2 = p >> 6, n4 = p & 63;
        int k = k2 * 2;
        float4 f0 = W2f4[k * 64 + n4];
        float4 f1 = W2f4[(k + 1) * 64 + n4];
        float a0[4] = {f0.x, f0.y, f0.z, f0.w};
        float a1[4] = {f1.x, f1.y, f1.z, f1.w};
        #pragma unroll
        for (int j = 0; j < 4; j++) {
            int n = n4 * 4 + j;
            __nv_bfloat16 h0 = __float2bfloat16(a0[j]);
            __nv_bfloat16 l0 = __float2bfloat16(a0[j] - __bfloat162float(h0));
            __nv_bfloat16 h1 = __float2bfloat16(a1[j]);
            __nv_bfloat16 l1 = __float2bfloat16(a1[j] - __bfloat162float(h1));
            uint32_t off = (uint32_t)n * STR_B + (uint32_t)k * 2u;
            __nv_bfloat162 hv; hv.x = h0; hv.y = h1;
            __nv_bfloat162 lv; lv.x = l0; lv.y = l1;
            *(__nv_bfloat162*)(smem + OFF_BHI + off) = hv;
            *(__nv_bfloat162*)(smem + OFF_BLO + off) = lv;
        }
    }

    // ---- stage m1 -> A_hi/A_lo as [m][k] rows (stride 272B) ----
    {
        int m = t >> 2;
        int src = s_src[m];
        int qrow = is_self ? (tile * 128 + m) : (tile * 4 + (m >> 5));
        const float4* A2f4 = (const float4*)g_A2 + (size_t)src * 32;
        const float4* P1f4 = (const float4*)g_P1 + (size_t)qrow * 32;
        #pragma unroll
        for (int i = 0; i < 8; i++) {
            int c4 = (t & 3) * 8 + i;
            float4 a = A2f4[c4], pp = P1f4[c4];
            float v[4] = {fmaxf(a.x - pp.x, 0.f), fmaxf(a.y - pp.y, 0.f),
                          fmaxf(a.z - pp.z, 0.f), fmaxf(a.w - pp.w, 0.f)};
            int c = c4 * 4;
            #pragma unroll
            for (int jj = 0; jj < 2; jj++) {
                int cc = c + jj * 2;
                __nv_bfloat16 h0 = __float2bfloat16(v[jj*2]);
                __nv_bfloat16 l0 = __float2bfloat16(v[jj*2] - __bfloat162float(h0));
                __nv_bfloat16 h1 = __float2bfloat16(v[jj*2+1]);
                __nv_bfloat16 l1 = __float2bfloat16(v[jj*2+1] - __bfloat162float(h1));
                uint32_t off = (uint32_t)m * STR_B + (uint32_t)cc * 2u;
                __nv_bfloat162 hv; hv.x = h0; hv.y = h1;
                __nv_bfloat162 lv; lv.x = l0; lv.y = l1;
                *(__nv_bfloat162*)(smem + OFF_AHI + off) = hv;
                *(__nv_bfloat162*)(smem + OFF_ALO + off) = lv;
            }
        }
    }
    __syncthreads();

    // ---- warp MMA: warp = (M 32 rows) x (N 64 cols); 3 terms x 8 k-steps ----
    int ms = (w >> 2) * 32, ns = (w & 3) * 64;
    uint32_t dynbase = smem_u32(smem);

    float acc[2][8][4];
    #pragma unroll
    for (int mt = 0; mt < 2; mt++)
        #pragma unroll
        for (int nt = 0; nt < 8; nt++)
            #pragma unroll
            for (int c = 0; c < 4; c++) acc[mt][nt][c] = 0.f;

    uint32_t arow = (uint32_t)(ms + (lane & 15));
    uint32_t acolx = (uint32_t)((lane >> 4) << 4);
    uint32_t brow = (uint32_t)(ns + (lane & 7));
    uint32_t bcolx = (uint32_t)(((lane >> 3) & 1) << 4);

    #pragma unroll 1
    for (int term = 0; term < 3; term++) {
        uint32_t Ao = dynbase + ((term == 2) ? OFF_ALO : OFF_AHI);
        uint32_t Bo = dynbase + ((term == 1) ? OFF_BLO : OFF_BHI);
        #pragma unroll 1
        for (int ks = 0; ks < 8; ks++) {
            uint32_t kb = (uint32_t)ks * 32u;
            uint32_t a[2][4];
            ldsm_x4(a[0][0], a[0][1], a[0][2], a[0][3],
                    Ao + arow * STR_B + kb + acolx);
            ldsm_x4(a[1][0], a[1][1], a[1][2], a[1][3],
                    Ao + (arow + 16u) * STR_B + kb + acolx);
            #pragma unroll
            for (int nt = 0; nt < 8; nt++) {
                uint32_t b0, b1;
                ldsm_x2(b0, b1, Bo + (brow + (uint32_t)nt * 8u) * STR_B + kb + bcolx);
                mma_bf16(acc[0][nt], a[0], b0, b1);
                mma_bf16(acc[1][nt], a[1], b0, b1);
            }
        }
    }

    // ---- epilogue ----
    int g = lane >> 2, tt = lane & 3;
    if (!is_self) {
        int q = tile * 4 + (w >> 2);
        int* ob = (int*)out + (size_t)q * 256;
        #pragma unroll
        for (int nt = 0; nt < 8; nt++) {
            int col0 = ns + nt * 8 + 2 * tt;
            float v0 = fmaxf(fmaxf(acc[0][nt][0], acc[0][nt][2]),
                             fmaxf(acc[1][nt][0], acc[1][nt][2]));
            float v1 = fmaxf(fmaxf(acc[0][nt][1], acc[0][nt][3]),
                             fmaxf(acc[1][nt][1], acc[1][nt][3]));
            v0 = fmaxf(v0 + b2s[col0], 0.f);
            v1 = fmaxf(v1 + b2s[col0 + 1], 0.f);
            #pragma unroll
            for (int off = 4; off <= 16; off <<= 1) {
                v0 = fmaxf(v0, __shfl_xor_sync(0xffffffffu, v0, off));
                v1 = fmaxf(v1, __shfl_xor_sync(0xffffffffu, v1, off));
            }
            if (lane < 4) {
                atomicMax(ob + col0,     __float_as_int(v0));
                atomicMax(ob + col0 + 1, __float_as_int(v1));
            }
        }
    } else {
        int rbase = tile * 128 + ms + g;
        #pragma unroll
        for (int mt = 0; mt < 2; mt++) {
            int r0 = rbase + mt * 16;
            int* o0 = (int*)out + (size_t)r0 * 256;
            int* o1 = (int*)out + (size_t)(r0 + 8) * 256;
            #pragma unroll
            for (int nt = 0; nt < 8; nt++) {
                int col0 = ns + nt * 8 + 2 * tt;
                float b0v = b2s[col0], b1v = b2s[col0 + 1];
                atomicMax(o0 + col0,     __float_as_int(fmaxf(acc[mt][nt][0] + b0v, 0.f)));
                atomicMax(o0 + col0 + 1, __float_as_int(fmaxf(acc[mt][nt][1] + b1v, 0.f)));
                atomicMax(o1 + col0,     __float_as_int(fmaxf(acc[mt][nt][2] + b0v, 0.f)));
                atomicMax(o1 + col0 + 1, __float_as_int(fmaxf(acc[mt][nt][3] + b1v, 0.f)));
            }
        }
    }
}

// =====================================================================
// launch
// inputs: 0:x1 1:pos1 2:batch1 3:x2 4:pos2 5:batch2 6:W1 7:b1 8:W2 9:b2
// =====================================================================
extern "C" void kernel_launch(void* const* d_in, const int* in_sizes, int n_in,
                              void* d_out, int out_size) {
    const float* pos1 = (const float*)d_in[1];
    const float* x2   = (const float*)d_in[3];
    const float* pos2 = (const float*)d_in[4];
    const float* W1   = (const float*)d_in[6];
    const float* b1   = (const float*)d_in[7];
    const float* W2   = (const float*)d_in[8];
    const float* b2   = (const float*)d_in[9];
    float* out = (float*)d_out;

    zero_out_kernel<<<4096, 256>>>((float4*)out);
    ball_query_kernel<<<NQ1/8, 256>>>(pos1, pos2);
    precompute_A2_kernel<<<NS2/16, 256>>>(x2, pos2, W1, b1);
    precompute_P1_kernel<<<(NQ1*128)/256, 256>>>(pos1, W1);

    cudaFuncSetAttribute(mma_layer2_kernel,
                         cudaFuncAttributeMaxDynamicSharedMemorySize,
                         DSMEM_BYTES);
    mma_layer2_kernel<<<4096 + 128, 512, DSMEM_BYTES>>>(W2, b2, out);
}